// round 12
// baseline (speedup 1.0000x reference)
#include <cuda_runtime.h>
#include <cuda_bf16.h>
#include <cstdint>

#define NPTS 8192
#define D 200
#define ROW_BYTES 512              // bf16 rows zero-padded to 256 k in global
#define NKS 13                     // 13 k-steps of 16 bf16 (K=208 covers D=200)
#define KBYTES 416                 // 208 bf16 = 416 bytes per row in smem
#define NCP (KBYTES / 16)          // 26 cp.async per row
#define TM 128
#define NT (NPTS / TM)             // 64
#define NTRI (NT * (NT + 1) / 2)   // 2080
#define TPB 256
#define SROW 432                   // 416 + 16 pad; 432 mod 128 = 48 -> conflict-free
#define ACH (TM * SROW)            // 55296
#define SMEM_DYN (2 * ACH)         // 110592 (A + B); 2 CTAs/SM = 216 KB + static

// ---------------- device scratch (no allocations allowed) ----------------
__device__ __align__(16) unsigned char g_xb[(size_t)NPTS * ROW_BYTES]; // 4 MB bf16
__device__ float g_sq[NPTS];
__device__ float g_part[NTRI];
__device__ int   g_is64;
__device__ unsigned int g_cnt;

#define CP16(d, s) \
    asm volatile("cp.async.cg.shared.global [%0], [%1], 16;" :: "r"(d), "l"(s) : "memory")
#define CPC()  asm volatile("cp.async.commit_group;" ::: "memory")
#define CPW0() asm volatile("cp.async.wait_group 0;" ::: "memory")

// ---------------------------------------------------------------------------
// Kernel 1: x -> bf16 (zero-padded), sq from the SAME bf16 values.
// Block 0 additionally: label-dtype detection + counter reset.
// ---------------------------------------------------------------------------
__global__ void prep_kernel(const float* __restrict__ x,
                            const int* __restrict__ lab32) {
    int row  = blockIdx.x * (TPB / 32) + (threadIdx.x >> 5);
    int lane = threadIdx.x & 31;
    int k0   = lane * 8;
    const float* xr = x + (size_t)row * D;
    float s = 0.f;
    uint32_t w[4];
#pragma unroll
    for (int p = 0; p < 4; p++) {
        int ka = k0 + 2 * p, kb = ka + 1;
        float f0 = (ka < D) ? xr[ka] : 0.f;
        float f1 = (kb < D) ? xr[kb] : 0.f;
        __nv_bfloat16 b0 = __float2bfloat16(f0);
        __nv_bfloat16 b1 = __float2bfloat16(f1);
        float g0 = __bfloat162float(b0), g1 = __bfloat162float(b1);
        s = fmaf(g0, g0, s);
        s = fmaf(g1, g1, s);
        w[p] = (uint32_t)__bfloat16_as_ushort(b0) |
               ((uint32_t)__bfloat16_as_ushort(b1) << 16);
    }
    *(uint4*)(g_xb + (size_t)row * ROW_BYTES + k0 * 2) = make_uint4(w[0], w[1], w[2], w[3]);
#pragma unroll
    for (int o = 16; o; o >>= 1) s += __shfl_xor_sync(0xffffffffu, s, o);
    if (lane == 0) g_sq[row] = s;

    if (blockIdx.x == 0) {  // label dtype detection + counter reset
        __shared__ int any;
        if (threadIdx.x == 0) { any = 0; g_cnt = 0; }
        __syncthreads();
        int a = 0;
        for (int i = 2 * threadIdx.x + 1; i < NPTS; i += 2 * TPB) a |= lab32[i];
        if (a) atomicOr(&any, 1);
        __syncthreads();
        if (threadIdx.x == 0) g_is64 = (any == 0) ? 1 : 0;
    }
}

// ---------------------------------------------------------------------------
// Kernel 2: triangular grid of 128x128 Gram tiles, mma.sync bf16 m16n8k16.
// Whole K=208 resident in smem (row stride 432B: natively conflict-free).
// One load phase, one sync, then 13 barrier-free k-steps with
// immediate-offset ldmatrix addresses (no swizzle ALU).
// ---------------------------------------------------------------------------
__global__ void __launch_bounds__(TPB, 2)
pair_kernel(const int* __restrict__ lab32, float* __restrict__ out) {
    extern __shared__ __align__(128) unsigned char dyn[];
    __shared__ float sqA[TM], sqB[TM];
    __shared__ int   lA[TM], lB[TM];
    __shared__ float red[TPB / 32];
    __shared__ int   s_last;

    const int t    = threadIdx.x;
    const int wid  = t >> 5;
    const int lane = t & 31;

    // linearized upper-triangle map: blockIdx.x -> (ti, tj), ti <= tj
    int bl = blockIdx.x, ti = 0;
    while (bl >= NT - ti) { bl -= NT - ti; ti++; }
    const int tj = ti + bl;

    const uint32_t dynA = (uint32_t)__cvta_generic_to_shared(dyn);
    const unsigned char* gA = g_xb + (size_t)(ti * TM) * ROW_BYTES;
    const unsigned char* gB = g_xb + (size_t)(tj * TM) * ROW_BYTES;

    // ---- single load phase: both 128x416B tiles via cp.async ----
    {
        int row = t & 127, op = t >> 7;
        const unsigned char* gp = op ? gB : gA;
        uint32_t dst = dynA + (op ? (uint32_t)ACH : 0u) + row * SROW;
        const unsigned char* src = gp + (size_t)row * ROW_BYTES;
#pragma unroll
        for (int c = 0; c < NCP; c++)
            CP16(dst + c * 16, src + c * 16);
        CPC();
    }

    {
        int is64 = g_is64;
        if (t < TM) {
            int g = ti * TM + t;
            sqA[t] = g_sq[g];
            lA[t]  = is64 ? lab32[2 * g] : lab32[g];
        } else {
            int u = t - TM, g = tj * TM + u;
            sqB[u] = g_sq[g];
            lB[u]  = is64 ? lab32[2 * g] : lab32[g];
        }
    }

    const int warp_m = wid >> 1;   // 0..3 -> 32 rows
    const int warp_n = wid & 1;    // 0..1 -> 64 cols

    // Immediate-offset ldmatrix bases; k advances by ks*32 bytes.
    uint32_t abase[2];
#pragma unroll
    for (int f = 0; f < 2; f++)
        abase[f] = dynA + (warp_m * 32 + f * 16 + (lane & 15)) * SROW
                 + ((lane >> 4) << 4);
    uint32_t bbase[4];
#pragma unroll
    for (int h = 0; h < 4; h++)
        bbase[h] = dynA + ACH
                 + (warp_n * 64 + h * 16 + (lane & 7) + ((lane >> 4) << 3)) * SROW
                 + (((lane >> 3) & 1) << 4);

    float acc[2][8][4];
#pragma unroll
    for (int f = 0; f < 2; f++)
#pragma unroll
        for (int j = 0; j < 8; j++)
#pragma unroll
            for (int e = 0; e < 4; e++) acc[f][j][e] = 0.f;

    CPW0();
    __syncthreads();

    // ---- 13 barrier-free k-steps ----
#pragma unroll
    for (int ks = 0; ks < NKS; ks++) {
        uint32_t a_[2][4];
#pragma unroll
        for (int f = 0; f < 2; f++)
            asm volatile("ldmatrix.sync.aligned.m8n8.x4.shared.b16 {%0,%1,%2,%3}, [%4];"
                : "=r"(a_[f][0]), "=r"(a_[f][1]), "=r"(a_[f][2]), "=r"(a_[f][3])
                : "r"(abase[f] + ks * 32));
#pragma unroll
        for (int h = 0; h < 4; h++) {
            uint32_t b0_, b1_, b2_, b3_;
            asm volatile("ldmatrix.sync.aligned.m8n8.x4.shared.b16 {%0,%1,%2,%3}, [%4];"
                : "=r"(b0_), "=r"(b1_), "=r"(b2_), "=r"(b3_)
                : "r"(bbase[h] + ks * 32));
#pragma unroll
            for (int f = 0; f < 2; f++) {
                asm volatile(
                    "mma.sync.aligned.m16n8k16.row.col.f32.bf16.bf16.f32 "
                    "{%0,%1,%2,%3}, {%4,%5,%6,%7}, {%8,%9}, {%0,%1,%2,%3};"
                    : "+f"(acc[f][2 * h][0]), "+f"(acc[f][2 * h][1]),
                      "+f"(acc[f][2 * h][2]), "+f"(acc[f][2 * h][3])
                    : "r"(a_[f][0]), "r"(a_[f][1]), "r"(a_[f][2]), "r"(a_[f][3]),
                      "r"(b0_), "r"(b1_));
                asm volatile(
                    "mma.sync.aligned.m16n8k16.row.col.f32.bf16.bf16.f32 "
                    "{%0,%1,%2,%3}, {%4,%5,%6,%7}, {%8,%9}, {%0,%1,%2,%3};"
                    : "+f"(acc[f][2 * h + 1][0]), "+f"(acc[f][2 * h + 1][1]),
                      "+f"(acc[f][2 * h + 1][2]), "+f"(acc[f][2 * h + 1][3])
                    : "r"(a_[f][0]), "r"(a_[f][1]), "r"(a_[f][2]), "r"(a_[f][3]),
                      "r"(b2_), "r"(b3_));
            }
        }
    }

    // Epilogue: d2 -> dist -> signed, strict upper (gn > gm) predicate.
    float lsum = 0.f;
    const int qrow = lane >> 2;
    const int qcol = (lane & 3) * 2;
#pragma unroll
    for (int f = 0; f < 2; f++) {
        int m0 = warp_m * 32 + f * 16 + qrow;
#pragma unroll
        for (int j = 0; j < 8; j++) {
            int n0 = warp_n * 64 + j * 8 + qcol;
#pragma unroll
            for (int e = 0; e < 4; e++) {
                int m_loc = m0 + ((e >> 1) << 3);
                int n_loc = n0 + (e & 1);
                int gm = ti * TM + m_loc;
                int gn = tj * TM + n_loc;
                float d2   = sqA[m_loc] + sqB[n_loc] - 2.f * acc[f][j][e];
                float dist = sqrtf(fmaxf(d2, 0.f));
                float sgn  = (lA[m_loc] == lB[n_loc]) ? dist : -dist;
                if (gn > gm) lsum += sgn;
            }
        }
    }
#pragma unroll
    for (int o = 16; o; o >>= 1) lsum += __shfl_xor_sync(0xffffffffu, lsum, o);
    if (lane == 0) red[wid] = lsum;
    __syncthreads();
    if (t == 0) {
        float s = 0.f;
#pragma unroll
        for (int w = 0; w < TPB / 32; w++) s += red[w];
        g_part[blockIdx.x] = s;
    }

    // ---- last-CTA-done fused final reduction (deterministic order) ----
    // dred lives in the (now unused) dynamic tile region.
    double* dred = (double*)dyn;
    __threadfence();
    if (t == 0) {
        unsigned old = atomicAdd(&g_cnt, 1u);
        s_last = (old == NTRI - 1) ? 1 : 0;
    }
    __syncthreads();
    if (s_last) {
        __threadfence();
        double a = 0.0;
        for (int i = t; i < NTRI; i += TPB) a += (double)g_part[i];
        dred[t] = a;
        __syncthreads();
        for (int o = TPB / 2; o; o >>= 1) {
            if (t < o) dred[t] += dred[t + o];
            __syncthreads();
        }
        if (t == 0) out[0] = (float)(2.0 * dred[0] / (double)NPTS);
    }
}

// ---------------------------------------------------------------------------
extern "C" void kernel_launch(void* const* d_in, const int* in_sizes, int n_in,
                              void* d_out, int out_size) {
    const float* x     = (const float*)d_in[0];
    const int*   lab32 = (const int*)d_in[1];
    float*       outp  = (float*)d_out;

    cudaFuncSetAttribute(pair_kernel, cudaFuncAttributeMaxDynamicSharedMemorySize,
                         SMEM_DYN);

    prep_kernel<<<NPTS / (TPB / 32), TPB>>>(x, lab32);
    pair_kernel<<<NTRI, TPB, SMEM_DYN>>>(lab32, outp);
}

// round 13
// speedup vs baseline: 1.5634x; 1.5634x over previous
#include <cuda_runtime.h>
#include <cuda_bf16.h>
#include <cstdint>

#define NPTS 8192
#define D 200
#define ROW_BYTES 512              // bf16 rows zero-padded to 256 k in global
#define TM 128
#define NT (NPTS / TM)             // 64
#define NTRI (NT * (NT + 1) / 2)   // 2080
#define TPB 256
#define SROW 144                   // 128B chunk row + 16 pad -> conflict-free
#define ACH (TM * SROW)            // 18432
#define STAGE (2 * ACH)            // A + B per stage = 36864
#define SMEM_DYN (2 * STAGE)       // double buffer = 73728

// ---------------- device scratch (no allocations allowed) ----------------
__device__ __align__(16) unsigned char g_xb[(size_t)NPTS * ROW_BYTES]; // 4 MB bf16
__device__ float g_sq[NPTS];
__device__ float g_part[NTRI];
__device__ int   g_is64;
__device__ unsigned int g_cnt;

#define CP16(d, s) \
    asm volatile("cp.async.cg.shared.global [%0], [%1], 16;" :: "r"(d), "l"(s) : "memory")
#define CPC()  asm volatile("cp.async.commit_group;" ::: "memory")
#define CPW1() asm volatile("cp.async.wait_group 1;" ::: "memory")
#define CPW0() asm volatile("cp.async.wait_group 0;" ::: "memory")

// ---------------------------------------------------------------------------
// Kernel 1: x -> bf16 (zero-padded), sq from the SAME bf16 values.
// Block 0 additionally: label-dtype detection + counter reset.
// ---------------------------------------------------------------------------
__global__ void prep_kernel(const float* __restrict__ x,
                            const int* __restrict__ lab32) {
    int row  = blockIdx.x * (TPB / 32) + (threadIdx.x >> 5);
    int lane = threadIdx.x & 31;
    int k0   = lane * 8;
    const float* xr = x + (size_t)row * D;
    float s = 0.f;
    uint32_t w[4];
#pragma unroll
    for (int p = 0; p < 4; p++) {
        int ka = k0 + 2 * p, kb = ka + 1;
        float f0 = (ka < D) ? xr[ka] : 0.f;
        float f1 = (kb < D) ? xr[kb] : 0.f;
        __nv_bfloat16 b0 = __float2bfloat16(f0);
        __nv_bfloat16 b1 = __float2bfloat16(f1);
        float g0 = __bfloat162float(b0), g1 = __bfloat162float(b1);
        s = fmaf(g0, g0, s);
        s = fmaf(g1, g1, s);
        w[p] = (uint32_t)__bfloat16_as_ushort(b0) |
               ((uint32_t)__bfloat16_as_ushort(b1) << 16);
    }
    *(uint4*)(g_xb + (size_t)row * ROW_BYTES + k0 * 2) = make_uint4(w[0], w[1], w[2], w[3]);
#pragma unroll
    for (int o = 16; o; o >>= 1) s += __shfl_xor_sync(0xffffffffu, s, o);
    if (lane == 0) g_sq[row] = s;

    if (blockIdx.x == 0) {  // label dtype detection + counter reset
        __shared__ int any;
        if (threadIdx.x == 0) { any = 0; g_cnt = 0; }
        __syncthreads();
        int a = 0;
        for (int i = 2 * threadIdx.x + 1; i < NPTS; i += 2 * TPB) a |= lab32[i];
        if (a) atomicOr(&any, 1);
        __syncthreads();
        if (threadIdx.x == 0) g_is64 = (any == 0) ? 1 : 0;
    }
}

// ---------------------------------------------------------------------------
// Chunk prefetch: 128B of K per row for A(128) + B(128) rows into stage buf.
// ---------------------------------------------------------------------------
__device__ __forceinline__ void prefetch(uint32_t dynA, int buf,
                                         const unsigned char* gA,
                                         const unsigned char* gB, int ch, int t) {
    uint32_t so = buf ? (uint32_t)STAGE : 0u;
#pragma unroll
    for (int p = 0; p < 8; p++) {
        int G = t + TPB * p;                 // 0..2047
        int isB  = (G >= 1024);
        int L    = isB ? (G - 1024) : G;
        int row  = L >> 3, g = L & 7;
        const unsigned char* gp = isB ? gB : gA;
        uint32_t soff = so + (isB ? (uint32_t)ACH : 0u) + row * SROW + g * 16;
        size_t   goff = (size_t)row * ROW_BYTES + (size_t)ch * 128 + (size_t)g * 16;
        CP16(dynA + soff, gp + goff);
    }
    CPC();
}

// ---------------------------------------------------------------------------
// Kernel 2: triangular grid of 128x128 Gram tiles, mma.sync bf16 m16n8k16.
// Chunked cp.async double buffer + EXPLICIT register double-buffering of
// ldmatrix fragments: at h-stage s, issue LDSM for s+1, then 4 HMMAs for s.
// ---------------------------------------------------------------------------
__global__ void __launch_bounds__(TPB, 2)
pair_kernel(const int* __restrict__ lab32, float* __restrict__ out) {
    extern __shared__ __align__(128) unsigned char dyn[];
    __shared__ float sqA[TM], sqB[TM];
    __shared__ int   lA[TM], lB[TM];
    __shared__ float red[TPB / 32];
    __shared__ int    s_last;
    __shared__ double dred[TPB];

    const int t    = threadIdx.x;
    const int wid  = t >> 5;
    const int lane = t & 31;

    // linearized upper-triangle map: blockIdx.x -> (ti, tj), ti <= tj
    int bl = blockIdx.x, ti = 0;
    while (bl >= NT - ti) { bl -= NT - ti; ti++; }
    const int tj = ti + bl;

    const uint32_t dynA = (uint32_t)__cvta_generic_to_shared(dyn);
    const unsigned char* gA = g_xb + (size_t)(ti * TM) * ROW_BYTES;
    const unsigned char* gB = g_xb + (size_t)(tj * TM) * ROW_BYTES;

    prefetch(dynA, 0, gA, gB, 0, t);
    prefetch(dynA, 1, gA, gB, 1, t);

    {
        int is64 = g_is64;
        if (t < TM) {
            int g = ti * TM + t;
            sqA[t] = g_sq[g];
            lA[t]  = is64 ? lab32[2 * g] : lab32[g];
        } else {
            int u = t - TM, g = tj * TM + u;
            sqB[u] = g_sq[g];
            lB[u]  = is64 ? lab32[2 * g] : lab32[g];
        }
    }

    const int warp_m = wid >> 1;   // 0..3 -> 32 rows
    const int warp_n = wid & 1;    // 0..1 -> 64 cols

    // Padded-stride (conflict-free) immediate-offset ldmatrix bases.
    uint32_t abase[2];
#pragma unroll
    for (int f = 0; f < 2; f++)
        abase[f] = dynA + (warp_m * 32 + f * 16 + (lane & 15)) * SROW
                 + ((lane >> 4) << 4);
    uint32_t bbase[4];
#pragma unroll
    for (int h = 0; h < 4; h++)
        bbase[h] = dynA + ACH
                 + (warp_n * 64 + h * 16 + (lane & 7) + ((lane >> 4) << 3)) * SROW
                 + (((lane >> 3) & 1) << 4);

    float acc[2][8][4];
#pragma unroll
    for (int f = 0; f < 2; f++)
#pragma unroll
        for (int j = 0; j < 8; j++)
#pragma unroll
            for (int e = 0; e < 4; e++) acc[f][j][e] = 0.f;

    uint32_t aF[2][2][4];   // [kstep parity][f][frag]
    uint32_t bF[2][4];      // [stage parity][frag]

#define LDA_M(buf, kk)                                                            \
    { _Pragma("unroll")                                                           \
      for (int f = 0; f < 2; f++)                                                 \
          asm volatile("ldmatrix.sync.aligned.m8n8.x4.shared.b16 {%0,%1,%2,%3}, [%4];" \
              : "=r"(aF[buf][f][0]), "=r"(aF[buf][f][1]),                         \
                "=r"(aF[buf][f][2]), "=r"(aF[buf][f][3])                          \
              : "r"(abase[f] + bofs + (kk) * 32)); }

#define LDB_M(slot, kk, hh)                                                       \
    asm volatile("ldmatrix.sync.aligned.m8n8.x4.shared.b16 {%0,%1,%2,%3}, [%4];"  \
        : "=r"(bF[slot][0]), "=r"(bF[slot][1]), "=r"(bF[slot][2]), "=r"(bF[slot][3]) \
        : "r"(bbase[hh] + bofs + (kk) * 32))

#define MMA4_M(abuf, slot, hh)                                                    \
    { _Pragma("unroll")                                                           \
      for (int f = 0; f < 2; f++) {                                               \
          asm volatile(                                                           \
              "mma.sync.aligned.m16n8k16.row.col.f32.bf16.bf16.f32 "              \
              "{%0,%1,%2,%3}, {%4,%5,%6,%7}, {%8,%9}, {%0,%1,%2,%3};"             \
              : "+f"(acc[f][2 * (hh)][0]), "+f"(acc[f][2 * (hh)][1]),             \
                "+f"(acc[f][2 * (hh)][2]), "+f"(acc[f][2 * (hh)][3])              \
              : "r"(aF[abuf][f][0]), "r"(aF[abuf][f][1]),                         \
                "r"(aF[abuf][f][2]), "r"(aF[abuf][f][3]),                         \
                "r"(bF[slot][0]), "r"(bF[slot][1]));                              \
          asm volatile(                                                           \
              "mma.sync.aligned.m16n8k16.row.col.f32.bf16.bf16.f32 "              \
              "{%0,%1,%2,%3}, {%4,%5,%6,%7}, {%8,%9}, {%0,%1,%2,%3};"             \
              : "+f"(acc[f][2 * (hh) + 1][0]), "+f"(acc[f][2 * (hh) + 1][1]),     \
                "+f"(acc[f][2 * (hh) + 1][2]), "+f"(acc[f][2 * (hh) + 1][3])      \
              : "r"(aF[abuf][f][0]), "r"(aF[abuf][f][1]),                         \
                "r"(aF[abuf][f][2]), "r"(aF[abuf][f][3]),                         \
                "r"(bF[slot][2]), "r"(bF[slot][3]));                              \
      } }

// Pipelined chunk: NS ksteps = 4*NS h-stages; LDSM for s+1 precedes MMA for s.
#define CHUNK_M(NS)                                                               \
    do {                                                                          \
        LDA_M(0, 0);                                                              \
        LDB_M(0, 0, 0);                                                           \
        _Pragma("unroll")                                                         \
        for (int s = 0; s < 4 * (NS); s++) {                                      \
            int ks = s >> 2, h = s & 3;                                           \
            int sn = s + 1, kn = sn >> 2, hn = sn & 3;                            \
            if (sn < 4 * (NS)) {                                                  \
                if (hn == 0) LDA_M(kn & 1, kn);                                   \
                LDB_M(sn & 1, kn, hn);                                            \
            }                                                                     \
            MMA4_M(ks & 1, s & 1, h);                                             \
        }                                                                         \
    } while (0)

#pragma unroll
    for (int ch = 0; ch < 4; ch++) {
        if (ch < 3) CPW1(); else CPW0();
        __syncthreads();
        const uint32_t bofs = (ch & 1) ? (uint32_t)STAGE : 0u;
        if (ch < 3) CHUNK_M(4); else CHUNK_M(1);   // 13 k-steps total
        __syncthreads();
        if (ch < 2) prefetch(dynA, ch & 1, gA, gB, ch + 2, t);
    }
#undef CHUNK_M
#undef MMA4_M
#undef LDB_M
#undef LDA_M

    // Epilogue: d2 -> dist (approx sqrt) -> signed, strict upper predicate.
    float lsum = 0.f;
    const int qrow = lane >> 2;
    const int qcol = (lane & 3) * 2;
#pragma unroll
    for (int f = 0; f < 2; f++) {
        int m0 = warp_m * 32 + f * 16 + qrow;
#pragma unroll
        for (int j = 0; j < 8; j++) {
            int n0 = warp_n * 64 + j * 8 + qcol;
#pragma unroll
            for (int e = 0; e < 4; e++) {
                int m_loc = m0 + ((e >> 1) << 3);
                int n_loc = n0 + (e & 1);
                int gm = ti * TM + m_loc;
                int gn = tj * TM + n_loc;
                float d2 = fmaxf(sqA[m_loc] + sqB[n_loc] - 2.f * acc[f][j][e], 0.f);
                float dist;
                asm("sqrt.approx.f32 %0, %1;" : "=f"(dist) : "f"(d2));
                float sgn = (lA[m_loc] == lB[n_loc]) ? dist : -dist;
                if (gn > gm) lsum += sgn;
            }
        }
    }
#pragma unroll
    for (int o = 16; o; o >>= 1) lsum += __shfl_xor_sync(0xffffffffu, lsum, o);
    if (lane == 0) red[wid] = lsum;
    __syncthreads();
    if (t == 0) {
        float s = 0.f;
#pragma unroll
        for (int w = 0; w < TPB / 32; w++) s += red[w];
        g_part[blockIdx.x] = s;
    }

    // ---- last-CTA-done fused final reduction (deterministic order) ----
    __threadfence();
    if (t == 0) {
        unsigned old = atomicAdd(&g_cnt, 1u);
        s_last = (old == NTRI - 1) ? 1 : 0;
    }
    __syncthreads();
    if (s_last) {
        __threadfence();
        double a = 0.0;
        for (int i = t; i < NTRI; i += TPB) a += (double)g_part[i];
        dred[t] = a;
        __syncthreads();
        for (int o = TPB / 2; o; o >>= 1) {
            if (t < o) dred[t] += dred[t + o];
            __syncthreads();
        }
        if (t == 0) out[0] = (float)(2.0 * dred[0] / (double)NPTS);
    }
}

// ---------------------------------------------------------------------------
extern "C" void kernel_launch(void* const* d_in, const int* in_sizes, int n_in,
                              void* d_out, int out_size) {
    const float* x     = (const float*)d_in[0];
    const int*   lab32 = (const int*)d_in[1];
    float*       outp  = (float*)d_out;

    cudaFuncSetAttribute(pair_kernel, cudaFuncAttributeMaxDynamicSharedMemorySize,
                         SMEM_DYN);

    prep_kernel<<<NPTS / (TPB / 32), TPB>>>(x, lab32);
    pair_kernel<<<NTRI, TPB, SMEM_DYN>>>(lab32, outp);
}